// round 9
// baseline (speedup 1.0000x reference)
#include <cuda_runtime.h>
#include <cuda_bf16.h>

// PosMLP, two kernels:
//  A) gen_weights: weights[q][65] = queries[q] @ w_gen^T + b_gen -> __device__ scratch.
//     Warp holds 4 queries in registers, 4-way n-split across warps (1800 warps).
//     Each w_gen row load feeds 4 dots; 6-shfl reduction per 4 outputs.
//  B) raster (round-6 proven body): thread = (q, w, h-half); 24 rows;
//     packed fma.rn.f32x2 inner loop.
//
// Shapes fixed by setup_inputs: B=2, Q=900 (NQ=1800), C=256, HIDDEN=16, H=W=48.

#define CC   256
#define NW   65
#define HD   16
#define HH   48
#define WW   48
#define NQ   1800

__device__ float g_wt[NQ * NW];   // 468 KB scratch (L2-resident)

// ---------------------------------------------------------------------------
// Kernel A: 225 blocks x 256 threads (8 warps) = 1800 warps.
// Warp gw -> (q4 = (gw>>2)*4, nsplit = gw&3). n-groups: nb = nsplit*4; nb += 16.
// Lane owns channels [lane*8, lane*8+8) via two float4 loads per row.
// ---------------------------------------------------------------------------
__global__ __launch_bounds__(256) void gen_weights_kernel(
    const float* __restrict__ queries,   // [1800][256]
    const float* __restrict__ w_gen,     // [65][256]
    const float* __restrict__ b_gen)     // [65]
{
    const int warp = threadIdx.x >> 5;
    const int lane = threadIdx.x & 31;
    const int gw   = blockIdx.x * 8 + warp;   // 0..1799
    const int q4   = (gw >> 2) * 4;           // base query (0,4,...,1796)
    const int ns   = gw & 3;

    // Hold 4 query rows' channels in registers: 8 x float4 = 32 regs.
    float4 qr[4][2];
    #pragma unroll
    for (int j = 0; j < 4; j++) {
        const float4* qrow = (const float4*)(queries + (size_t)(q4 + j) * CC);
        qr[j][0] = qrow[lane * 2];
        qr[j][1] = qrow[lane * 2 + 1];
    }

    const bool lo16 = (lane & 16) == 0;
    const bool lo8  = (lane & 8) == 0;

    for (int nb = ns * 4; nb < NW; nb += 16) {
        // s[j][r] = partial dot(query j, w_gen[nb+r]) over this lane's 8 channels
        float s[4][4];
        #pragma unroll
        for (int r = 0; r < 4; r++) {
            const int n = min(nb + r, NW - 1);   // clamp only matters at nb=64
            const float4* wr = (const float4*)(w_gen + (size_t)n * CC);
            const float4 w0 = wr[lane * 2];
            const float4 w1 = wr[lane * 2 + 1];
            #pragma unroll
            for (int j = 0; j < 4; j++) {
                float t0 = 0.f, t1 = 0.f;
                t0 = fmaf(qr[j][0].x, w0.x, t0);  t1 = fmaf(qr[j][0].y, w0.y, t1);
                t0 = fmaf(qr[j][0].z, w0.z, t0);  t1 = fmaf(qr[j][0].w, w0.w, t1);
                t0 = fmaf(qr[j][1].x, w1.x, t0);  t1 = fmaf(qr[j][1].y, w1.y, t1);
                t0 = fmaf(qr[j][1].z, w1.z, t0);  t1 = fmaf(qr[j][1].w, w1.w, t1);
                s[j][r] = t0 + t1;
            }
        }

        // For each query j: 6-shfl reduce of s[j][0..3]; result for value r
        // lands on lane 8*r (r = lane>>3).
        #pragma unroll
        for (int j = 0; j < 4; j++) {
            float a0 = lo16 ? s[j][0] : s[j][2];
            float b0 = lo16 ? s[j][2] : s[j][0];
            a0 += __shfl_xor_sync(0xffffffffu, b0, 16);
            float a1 = lo16 ? s[j][1] : s[j][3];
            float b1 = lo16 ? s[j][3] : s[j][1];
            a1 += __shfl_xor_sync(0xffffffffu, b1, 16);
            float c = lo8 ? a0 : a1;
            float d = lo8 ? a1 : a0;
            c += __shfl_xor_sync(0xffffffffu, d, 8);
            c += __shfl_xor_sync(0xffffffffu, c, 4);
            c += __shfl_xor_sync(0xffffffffu, c, 2);
            c += __shfl_xor_sync(0xffffffffu, c, 1);

            if ((lane & 7) == 0) {
                const int n = nb + (lane >> 3);
                if (n < NW)
                    g_wt[(q4 + j) * NW + n] = c + b_gen[n];
            }
        }
    }
}

// ---------------------------------------------------------------------------
// Packed fp32x2 FMA (sm_103a FFMA2 — only reachable via PTX fma.rn.f32x2).
// ---------------------------------------------------------------------------
union F2U { float2 f; unsigned long long u; };

__device__ __forceinline__ float2 ffma2(float2 a, float2 b, float2 c) {
    F2U A, B, C, D;
    A.f = a; B.f = b; C.f = c;
    asm("fma.rn.f32x2 %0, %1, %2, %3;"
        : "=l"(D.u) : "l"(A.u), "l"(B.u), "l"(C.u));
    return D.f;
}

// ---------------------------------------------------------------------------
// Kernel B: rasterizer (round-6 proven version).
// 1350 blocks x 128 threads. gtid -> q = gtid/96; hh = (gtid%96)/48; w = gtid%48.
// ---------------------------------------------------------------------------
__global__ __launch_bounds__(128) void raster_kernel(
    const float* __restrict__ pos,       // [1800][4] (cx, cy, bw, bh)
    float* __restrict__ out)             // [1800][48][48]
{
    const int gtid = blockIdx.x * 128 + threadIdx.x;
    const int q    = gtid / 96;
    const int rem  = gtid - q * 96;
    const int hh   = rem / 48;           // 0 or 1
    const int w    = rem - hh * 48;

    const float* __restrict__ wt = g_wt + q * NW;

    const float cx = pos[q * 4 + 0];
    const float cy = pos[q * 4 + 1];
    const float bw = pos[q * 4 + 2];
    const float bh = pos[q * 4 + 3];

    const float rx     = ((w + 0.5f) * (1.0f / WW) - cx) / bw;
    const float inv_bh = 1.0f / bh;

    // Pack per-pair (k = 2j, 2j+1) params. Fold rx*w1x + b1 into tw.
    float2 w1y2[HD / 2], tw2[HD / 2], w22[HD / 2];
    const float2 rx2 = make_float2(rx, rx);
    #pragma unroll
    for (int j = 0; j < HD / 2; j++) {
        w1y2[j]     = make_float2(wt[4 * j],     wt[4 * j + 2]);      // w1y_{2j}, w1y_{2j+1}
        float2 w1x2 = make_float2(wt[4 * j + 1], wt[4 * j + 3]);      // w1x_{2j}, w1x_{2j+1}
        float2 b12  = make_float2(wt[2 * HD + 2 * j], wt[2 * HD + 2 * j + 1]);
        tw2[j]      = ffma2(rx2, w1x2, b12);
        w22[j]      = make_float2(wt[3 * HD + 2 * j], wt[3 * HD + 2 * j + 1]);
    }
    const float b2 = wt[4 * HD];

    const int   h0    = hh * (HH / 2);
    const float y0    = ((h0 + 0.5f) * (1.0f / HH) - cy) * inv_bh;
    const float ystep = (1.0f / HH) * inv_bh;

    float* obase = out + (size_t)q * (HH * WW) + h0 * WW + w;

    #pragma unroll 2
    for (int h = 0; h < HH / 2; h++) {
        const float  ry  = fmaf((float)h, ystep, y0);
        const float2 ry2 = make_float2(ry, ry);
        float2 acc0 = make_float2(b2, 0.f);
        float2 acc1 = make_float2(0.f, 0.f);
        #pragma unroll
        for (int j = 0; j < HD / 2; j += 2) {
            float2 v0 = ffma2(ry2, w1y2[j],     tw2[j]);
            float2 v1 = ffma2(ry2, w1y2[j + 1], tw2[j + 1]);
            v0.x = fmaxf(v0.x, 0.f);  v0.y = fmaxf(v0.y, 0.f);
            v1.x = fmaxf(v1.x, 0.f);  v1.y = fmaxf(v1.y, 0.f);
            acc0 = ffma2(v0, w22[j],     acc0);
            acc1 = ffma2(v1, w22[j + 1], acc1);
        }
        obase[h * WW] = (acc0.x + acc0.y) + (acc1.x + acc1.y);
    }
}

extern "C" void kernel_launch(void* const* d_in, const int* in_sizes, int n_in,
                              void* d_out, int out_size) {
    const float* queries = (const float*)d_in[0];
    const float* pos     = (const float*)d_in[1];
    const float* w_gen   = (const float*)d_in[2];
    const float* b_gen   = (const float*)d_in[3];
    float* out = (float*)d_out;

    gen_weights_kernel<<<225, 256>>>(queries, w_gen, b_gen);
    raster_kernel<<<(NQ * WW * 2) / 128, 128>>>(pos, out);
}

// round 10
// speedup vs baseline: 1.0801x; 1.0801x over previous
#include <cuda_runtime.h>
#include <cuda_bf16.h>

// PosMLP, two kernels:
//  A) gen_weights: thread-per-output GEMM. Block = 4 queries x 64 n (256 thr),
//     queries staged in padded smem (LDS.128, conflict-free + broadcast),
//     w_gen rows via L1-cached LDG.128, inner product as 128 FFMA2 in 4 chains.
//     No shuffles. n=64 (b2 row) handled by 4 threads as a second output.
//  B) raster (round-6 proven body): thread = (q, w, h-half); 24 rows;
//     packed fma.rn.f32x2 inner loop.
//
// Shapes fixed by setup_inputs: B=2, Q=900 (NQ=1800), C=256, HIDDEN=16, H=W=48.

#define CC   256
#define NW   65
#define HD   16
#define HH   48
#define WW   48
#define NQ   1800
#define QPB  4            // queries per gen block
#define SPAD 264          // smem row stride (floats): 264 % 32 == 8 -> qi*8 bank offset

__device__ float g_wt[NQ * NW];   // 468 KB scratch (L2-resident)

// ---------------------------------------------------------------------------
// Packed fp32x2 FMA (sm_103a FFMA2 — only reachable via PTX fma.rn.f32x2).
// ---------------------------------------------------------------------------
union F2U { float2 f; unsigned long long u; };

__device__ __forceinline__ float2 ffma2(float2 a, float2 b, float2 c) {
    F2U A, B, C, D;
    A.f = a; B.f = b; C.f = c;
    asm("fma.rn.f32x2 %0, %1, %2, %3;"
        : "=l"(D.u) : "l"(A.u), "l"(B.u), "l"(C.u));
    return D.f;
}

// ---------------------------------------------------------------------------
// Kernel A: 450 blocks x 256 threads. tid -> (qi = tid&3, n = tid>>2).
// Warp = 8 n-rows x 4 qi. smem q reads broadcast across n; w reads share
// 8 lines per warp. 4 independent FFMA2 accumulator chains per thread.
// ---------------------------------------------------------------------------
__global__ __launch_bounds__(256) void gen_weights_kernel(
    const float* __restrict__ queries,   // [1800][256]
    const float* __restrict__ w_gen,     // [65][256]
    const float* __restrict__ b_gen)     // [65]
{
    __shared__ float shq[QPB][SPAD];

    const int tid   = threadIdx.x;
    const int qbase = blockIdx.x * QPB;

    // Stage 4 query rows (1024 floats) via 256 float4 loads.
    {
        const int r  = tid >> 6;        // 0..3
        const int c4 = tid & 63;        // 0..63
        float4 v = ((const float4*)(queries + (size_t)(qbase + r) * CC))[c4];
        float* dst = &shq[r][c4 * 4];
        dst[0] = v.x; dst[1] = v.y; dst[2] = v.z; dst[3] = v.w;
    }
    __syncthreads();

    const int qi = tid & 3;
    const int n  = tid >> 2;            // 0..63

    {
        const float4* w4 = (const float4*)(w_gen + (size_t)n * CC);
        const float4* q4 = (const float4*)&shq[qi][0];   // 16B-aligned (1056B row)
        float2 a0 = make_float2(0.f, 0.f), a1 = make_float2(0.f, 0.f);
        float2 a2 = make_float2(0.f, 0.f), a3 = make_float2(0.f, 0.f);
        #pragma unroll 8
        for (int i = 0; i < CC / 4; i += 2) {
            float4 wv0 = w4[i],     qv0 = q4[i];
            float4 wv1 = w4[i + 1], qv1 = q4[i + 1];
            a0 = ffma2(make_float2(qv0.x, qv0.y), make_float2(wv0.x, wv0.y), a0);
            a1 = ffma2(make_float2(qv0.z, qv0.w), make_float2(wv0.z, wv0.w), a1);
            a2 = ffma2(make_float2(qv1.x, qv1.y), make_float2(wv1.x, wv1.y), a2);
            a3 = ffma2(make_float2(qv1.z, qv1.w), make_float2(wv1.z, wv1.w), a3);
        }
        const float s = (a0.x + a0.y) + (a1.x + a1.y)
                      + (a2.x + a2.y) + (a3.x + a3.y);
        g_wt[(qbase + qi) * NW + n] = s + b_gen[n];
    }

    // Row n = 64 (b2): 4 threads take a second output each.
    if (tid < QPB) {
        const int qj = tid;
        const float4* w4 = (const float4*)(w_gen + (size_t)64 * CC);
        const float4* q4 = (const float4*)&shq[qj][0];
        float2 a0 = make_float2(0.f, 0.f), a1 = make_float2(0.f, 0.f);
        #pragma unroll 8
        for (int i = 0; i < CC / 4; i++) {
            float4 wv = w4[i], qv = q4[i];
            a0 = ffma2(make_float2(qv.x, qv.y), make_float2(wv.x, wv.y), a0);
            a1 = ffma2(make_float2(qv.z, qv.w), make_float2(wv.z, wv.w), a1);
        }
        g_wt[(qbase + qj) * NW + 64] = (a0.x + a0.y) + (a1.x + a1.y) + b_gen[64];
    }
}

// ---------------------------------------------------------------------------
// Kernel B: rasterizer (round-6 proven version, 62 regs).
// 1350 blocks x 128 threads. gtid -> q = gtid/96; hh = (gtid%96)/48; w = gtid%48.
// ---------------------------------------------------------------------------
__global__ __launch_bounds__(128) void raster_kernel(
    const float* __restrict__ pos,       // [1800][4] (cx, cy, bw, bh)
    float* __restrict__ out)             // [1800][48][48]
{
    const int gtid = blockIdx.x * 128 + threadIdx.x;
    const int q    = gtid / 96;
    const int rem  = gtid - q * 96;
    const int hh   = rem / 48;           // 0 or 1
    const int w    = rem - hh * 48;

    const float* __restrict__ wt = g_wt + q * NW;

    const float cx = pos[q * 4 + 0];
    const float cy = pos[q * 4 + 1];
    const float bw = pos[q * 4 + 2];
    const float bh = pos[q * 4 + 3];

    const float rx     = ((w + 0.5f) * (1.0f / WW) - cx) / bw;
    const float inv_bh = 1.0f / bh;

    // Pack per-pair (k = 2j, 2j+1) params. Fold rx*w1x + b1 into tw.
    float2 w1y2[HD / 2], tw2[HD / 2], w22[HD / 2];
    const float2 rx2 = make_float2(rx, rx);
    #pragma unroll
    for (int j = 0; j < HD / 2; j++) {
        w1y2[j]     = make_float2(wt[4 * j],     wt[4 * j + 2]);      // w1y_{2j}, w1y_{2j+1}
        float2 w1x2 = make_float2(wt[4 * j + 1], wt[4 * j + 3]);      // w1x_{2j}, w1x_{2j+1}
        float2 b12  = make_float2(wt[2 * HD + 2 * j], wt[2 * HD + 2 * j + 1]);
        tw2[j]      = ffma2(rx2, w1x2, b12);
        w22[j]      = make_float2(wt[3 * HD + 2 * j], wt[3 * HD + 2 * j + 1]);
    }
    const float b2 = wt[4 * HD];

    const int   h0    = hh * (HH / 2);
    const float y0    = ((h0 + 0.5f) * (1.0f / HH) - cy) * inv_bh;
    const float ystep = (1.0f / HH) * inv_bh;

    float* obase = out + (size_t)q * (HH * WW) + h0 * WW + w;

    #pragma unroll 2
    for (int h = 0; h < HH / 2; h++) {
        const float  ry  = fmaf((float)h, ystep, y0);
        const float2 ry2 = make_float2(ry, ry);
        float2 acc0 = make_float2(b2, 0.f);
        float2 acc1 = make_float2(0.f, 0.f);
        #pragma unroll
        for (int j = 0; j < HD / 2; j += 2) {
            float2 v0 = ffma2(ry2, w1y2[j],     tw2[j]);
            float2 v1 = ffma2(ry2, w1y2[j + 1], tw2[j + 1]);
            v0.x = fmaxf(v0.x, 0.f);  v0.y = fmaxf(v0.y, 0.f);
            v1.x = fmaxf(v1.x, 0.f);  v1.y = fmaxf(v1.y, 0.f);
            acc0 = ffma2(v0, w22[j],     acc0);
            acc1 = ffma2(v1, w22[j + 1], acc1);
        }
        obase[h * WW] = (acc0.x + acc0.y) + (acc1.x + acc1.y);
    }
}

extern "C" void kernel_launch(void* const* d_in, const int* in_sizes, int n_in,
                              void* d_out, int out_size) {
    const float* queries = (const float*)d_in[0];
    const float* pos     = (const float*)d_in[1];
    const float* w_gen   = (const float*)d_in[2];
    const float* b_gen   = (const float*)d_in[3];
    float* out = (float*)d_out;

    gen_weights_kernel<<<NQ / QPB, 256>>>(queries, w_gen, b_gen);
    raster_kernel<<<(NQ * WW * 2) / 128, 128>>>(pos, out);
}

// round 11
// speedup vs baseline: 1.1604x; 1.0743x over previous
#include <cuda_runtime.h>
#include <cuda_bf16.h>

// PosMLP, three kernels:
//  T) transpose w_gen [65][256] -> wb[c4][n] float4-blocked so that gen's
//     per-n loads are coalesced across lanes (4 lines/LDG.128, the HW minimum).
//  A) gen_weights v5: thread = (query-pair, n). 900 blocks x 96 threads.
//     Per c4 step: 1 coalesced wb load + 2 broadcast query loads + 4 FFMA2.
//     2 queries/thread halves w-traffic; no shuffles, no syncthreads.
//  B) raster (round-6 proven body): thread = (q, w, h-half); 24 rows;
//     packed fma.rn.f32x2 inner loop.
//
// Shapes fixed by setup_inputs: B=2, Q=900 (NQ=1800), C=256, HIDDEN=16, H=W=48.

#define CC   256
#define NW   65
#define HD   16
#define HH   48
#define WW   48
#define NQ   1800

__device__ float  g_wt[NQ * NW];        // 468 KB scratch (L2-resident)
__device__ float4 g_wb[64 * NW];        // transposed w_gen: g_wb[c4*65 + n] = w_gen[n][4c4..4c4+3]

// ---------------------------------------------------------------------------
// Packed fp32x2 FMA (sm_103a FFMA2 — only reachable via PTX fma.rn.f32x2).
// ---------------------------------------------------------------------------
union F2U { float2 f; unsigned long long u; };

__device__ __forceinline__ float2 ffma2(float2 a, float2 b, float2 c) {
    F2U A, B, C, D;
    A.f = a; B.f = b; C.f = c;
    asm("fma.rn.f32x2 %0, %1, %2, %3;"
        : "=l"(D.u) : "l"(A.u), "l"(B.u), "l"(C.u));
    return D.f;
}

// ---------------------------------------------------------------------------
// Kernel T: transpose. 4160 float4 elements; coalesced read, scattered write.
// ---------------------------------------------------------------------------
__global__ __launch_bounds__(128) void transpose_w_kernel(
    const float* __restrict__ w_gen)     // [65][256]
{
    const int gid = blockIdx.x * 128 + threadIdx.x;   // 0..4223
    if (gid >= NW * 64) return;
    const int n  = gid >> 6;          // 0..64
    const int c4 = gid & 63;          // 0..63
    g_wb[c4 * NW + n] = ((const float4*)w_gen)[gid];
}

// ---------------------------------------------------------------------------
// Kernel A: gen v5. 900 blocks x 96 threads; thread t (t<65) computes
// weights for queries (2b, 2b+1) at output n = t.
// wb loads: lanes consecutive n -> coalesced. q loads: warp-uniform broadcast.
// ---------------------------------------------------------------------------
__global__ __launch_bounds__(96) void gen_weights_kernel(
    const float* __restrict__ queries,   // [1800][256]
    const float* __restrict__ b_gen)     // [65]
{
    const int n = threadIdx.x;
    if (n >= NW) return;
    const int qp = blockIdx.x;           // 0..899

    const float4* __restrict__ q0 = (const float4*)(queries + (size_t)(2 * qp)     * CC);
    const float4* __restrict__ q1 = (const float4*)(queries + (size_t)(2 * qp + 1) * CC);
    const float4* __restrict__ wb = g_wb + n;

    float2 a00 = make_float2(0.f, 0.f), a01 = make_float2(0.f, 0.f);
    float2 a10 = make_float2(0.f, 0.f), a11 = make_float2(0.f, 0.f);

    #pragma unroll 8
    for (int c4 = 0; c4 < 64; c4++) {
        const float4 wv = wb[c4 * NW];
        const float4 x  = q0[c4];
        const float4 y  = q1[c4];
        a00 = ffma2(make_float2(x.x, x.y), make_float2(wv.x, wv.y), a00);
        a01 = ffma2(make_float2(x.z, x.w), make_float2(wv.z, wv.w), a01);
        a10 = ffma2(make_float2(y.x, y.y), make_float2(wv.x, wv.y), a10);
        a11 = ffma2(make_float2(y.z, y.w), make_float2(wv.z, wv.w), a11);
    }

    const float bg = b_gen[n];
    g_wt[(size_t)(2 * qp)     * NW + n] = (a00.x + a00.y) + (a01.x + a01.y) + bg;
    g_wt[(size_t)(2 * qp + 1) * NW + n] = (a10.x + a10.y) + (a11.x + a11.y) + bg;
}

// ---------------------------------------------------------------------------
// Kernel B: rasterizer (round-6 proven version, 62 regs).
// 1350 blocks x 128 threads. gtid -> q = gtid/96; hh = (gtid%96)/48; w = gtid%48.
// ---------------------------------------------------------------------------
__global__ __launch_bounds__(128) void raster_kernel(
    const float* __restrict__ pos,       // [1800][4] (cx, cy, bw, bh)
    float* __restrict__ out)             // [1800][48][48]
{
    const int gtid = blockIdx.x * 128 + threadIdx.x;
    const int q    = gtid / 96;
    const int rem  = gtid - q * 96;
    const int hh   = rem / 48;           // 0 or 1
    const int w    = rem - hh * 48;

    const float* __restrict__ wt = g_wt + q * NW;

    const float cx = pos[q * 4 + 0];
    const float cy = pos[q * 4 + 1];
    const float bw = pos[q * 4 + 2];
    const float bh = pos[q * 4 + 3];

    const float rx     = ((w + 0.5f) * (1.0f / WW) - cx) / bw;
    const float inv_bh = 1.0f / bh;

    // Pack per-pair (k = 2j, 2j+1) params. Fold rx*w1x + b1 into tw.
    float2 w1y2[HD / 2], tw2[HD / 2], w22[HD / 2];
    const float2 rx2 = make_float2(rx, rx);
    #pragma unroll
    for (int j = 0; j < HD / 2; j++) {
        w1y2[j]     = make_float2(wt[4 * j],     wt[4 * j + 2]);      // w1y_{2j}, w1y_{2j+1}
        float2 w1x2 = make_float2(wt[4 * j + 1], wt[4 * j + 3]);      // w1x_{2j}, w1x_{2j+1}
        float2 b12  = make_float2(wt[2 * HD + 2 * j], wt[2 * HD + 2 * j + 1]);
        tw2[j]      = ffma2(rx2, w1x2, b12);
        w22[j]      = make_float2(wt[3 * HD + 2 * j], wt[3 * HD + 2 * j + 1]);
    }
    const float b2 = wt[4 * HD];

    const int   h0    = hh * (HH / 2);
    const float y0    = ((h0 + 0.5f) * (1.0f / HH) - cy) * inv_bh;
    const float ystep = (1.0f / HH) * inv_bh;

    float* obase = out + (size_t)q * (HH * WW) + h0 * WW + w;

    #pragma unroll 2
    for (int h = 0; h < HH / 2; h++) {
        const float  ry  = fmaf((float)h, ystep, y0);
        const float2 ry2 = make_float2(ry, ry);
        float2 acc0 = make_float2(b2, 0.f);
        float2 acc1 = make_float2(0.f, 0.f);
        #pragma unroll
        for (int j = 0; j < HD / 2; j += 2) {
            float2 v0 = ffma2(ry2, w1y2[j],     tw2[j]);
            float2 v1 = ffma2(ry2, w1y2[j + 1], tw2[j + 1]);
            v0.x = fmaxf(v0.x, 0.f);  v0.y = fmaxf(v0.y, 0.f);
            v1.x = fmaxf(v1.x, 0.f);  v1.y = fmaxf(v1.y, 0.f);
            acc0 = ffma2(v0, w22[j],     acc0);
            acc1 = ffma2(v1, w22[j + 1], acc1);
        }
        obase[h * WW] = (acc0.x + acc0.y) + (acc1.x + acc1.y);
    }
}

extern "C" void kernel_launch(void* const* d_in, const int* in_sizes, int n_in,
                              void* d_out, int out_size) {
    const float* queries = (const float*)d_in[0];
    const float* pos     = (const float*)d_in[1];
    const float* w_gen   = (const float*)d_in[2];
    const float* b_gen   = (const float*)d_in[3];
    float* out = (float*)d_out;

    transpose_w_kernel<<<(NW * 64 + 127) / 128, 128>>>(w_gen);
    gen_weights_kernel<<<NQ / 2, 96>>>(queries, b_gen);
    raster_kernel<<<(NQ * WW * 2) / 128, 128>>>(pos, out);
}